// round 12
// baseline (speedup 1.0000x reference)
#include <cuda_runtime.h>
#include <stdint.h>

// Inputs (metadata order):
//   d_in[0] users      int32  [16384]   (JAX x64-disabled: int64 request -> int32)
//   d_in[1] items      int32  [16384]
//   d_in[2] bias_user  f32    [16384]
//   d_in[3] bias_item  f32    [16384]
//   d_in[4] o_avg      f32    [1]
//   d_in[5] c_score    f32    [1]   (unused)
//   d_in[6] user_table f32    [1000000 x 64]
//   d_in[7] item_table f32    [100000 x 64]
// Output: f32 [16384]

#define NUM_FACTORS 64
#define THREADS_PER_ROW 8   // each thread handles 8 floats (2 x float4) per table

__global__ __launch_bounds__(256)
void mf_dot_kernel(const int*   __restrict__ users,
                   const int*   __restrict__ items,
                   const float* __restrict__ bias_user,
                   const float* __restrict__ bias_item,
                   const float* __restrict__ o_avg,
                   const float* __restrict__ user_table,
                   const float* __restrict__ item_table,
                   float*       __restrict__ out,
                   int B)
{
    int tid   = blockIdx.x * blockDim.x + threadIdx.x;
    int row   = tid >> 3;        // 8 threads per row
    int lane8 = tid & 7;
    if (row >= B) return;

    // int32 indices; all 8 lanes of a group read the same word (L1 broadcast)
    long long u_idx = (long long)users[row];
    long long i_idx = (long long)items[row];

    const float4* up = reinterpret_cast<const float4*>(user_table + u_idx * NUM_FACTORS)
                       + (lane8 << 1);
    const float4* vp = reinterpret_cast<const float4*>(item_table + i_idx * NUM_FACTORS)
                       + (lane8 << 1);

    // Issue all 4 wide loads up front for max MLP before any FFMA dependency.
    float4 u0 = __ldg(up + 0);
    float4 u1 = __ldg(up + 1);
    float4 v0 = __ldg(vp + 0);
    float4 v1 = __ldg(vp + 1);

    float s = u0.x * v0.x;
    s = fmaf(u0.y, v0.y, s);
    s = fmaf(u0.z, v0.z, s);
    s = fmaf(u0.w, v0.w, s);
    s = fmaf(u1.x, v1.x, s);
    s = fmaf(u1.y, v1.y, s);
    s = fmaf(u1.z, v1.z, s);
    s = fmaf(u1.w, v1.w, s);

    // Tree-reduce within the contiguous 8-lane group; only lane 0's result is used.
    s += __shfl_down_sync(0xffffffffu, s, 4);
    s += __shfl_down_sync(0xffffffffu, s, 2);
    s += __shfl_down_sync(0xffffffffu, s, 1);

    if (lane8 == 0) {
        out[row] = s + bias_user[row] + bias_item[row] + o_avg[0];
    }
}

extern "C" void kernel_launch(void* const* d_in, const int* in_sizes, int n_in,
                              void* d_out, int out_size)
{
    const int*   users      = (const int*)d_in[0];
    const int*   items      = (const int*)d_in[1];
    const float* bias_user  = (const float*)d_in[2];
    const float* bias_item  = (const float*)d_in[3];
    const float* o_avg      = (const float*)d_in[4];
    // d_in[5] = c_score (unused)
    const float* user_table = (const float*)d_in[6];
    const float* item_table = (const float*)d_in[7];
    float*       out        = (float*)d_out;

    int B = out_size;                       // 16384
    int total_threads = B * THREADS_PER_ROW;
    int block = 256;
    int grid  = (total_threads + block - 1) / block;

    mf_dot_kernel<<<grid, block>>>(users, items, bias_user, bias_item, o_avg,
                                   user_table, item_table, out, B);
}